// round 14
// baseline (speedup 1.0000x reference)
#include <cuda_runtime.h>

#define P_ 2
#define B_ 96
#define A_ 32
#define N_ 3072        // B_*A_
#define NT_ 24
#define MD_ 4
#define MA_ 4
#define NPOL_ 8
#define CH_ 3          // j-range chunks per (pose,block)
#define TPB_ 256
#define NW_ (TPB_/32)
#define JCHUNK_ (N_/CH_)       // 1024 j atoms per CTA
#define JPW_ 128               // j atoms per warp
#define C_LK 0.0897935610625833f
#define FULLM 0xffffffffu

// Scratch (no allocations allowed)
__device__ double g_partial[P_*B_*CH_*2];
__device__ unsigned int g_done;   // zero-init; last CTA resets -> graph-replay safe

__device__ __forceinline__ int clampA(int v){ return min(max(v,0), A_-1); }

__global__ void __launch_bounds__(TPB_, 4) lkball_kernel(
    const float* __restrict__ coords,
    const int*   __restrict__ btype,
    const int*   __restrict__ minsep,
    const int*   __restrict__ bonds,     // (NT,A,2)
    const int*   __restrict__ ranges,    // (NT,A,2)
    const int*   __restrict__ n_donH,
    const int*   __restrict__ n_acc,
    const int*   __restrict__ donH_i,
    const int*   __restrict__ don_hvy_i,
    const int*   __restrict__ acc_i_arr,
    const int*   __restrict__ hyb_arr,
    const float* __restrict__ lkp,       // (NT,A,4) -> float4 aligned
    const int*   __restrict__ is_h,      // (NT,A)
    const int*   __restrict__ pathd,     // (NT,A,A)
    const float* __restrict__ lkgp,
    const float* __restrict__ wgp,
    const float* __restrict__ sp2t,
    const float* __restrict__ sp3t,
    const float* __restrict__ ringt,
    float*       __restrict__ out)
{
    __shared__ float4 s_pol[NPOL_], s_w0[NPOL_], s_w1[NPOL_];
    __shared__ unsigned s_pmask[NPOL_];     // same-block sep>=4 bit per atom-in-block
    __shared__ unsigned char s_sepok[B_];
    __shared__ short  s_bt[B_];
    __shared__ int    s_rng0[A_], s_b1[A_]; // this block-type's ranges[...,0], bonds[...,1]
    __shared__ float  s_cb[A_*3];           // this block's coords
    __shared__ float4 s_lkprow[A_];         // lkp row for this block type
    __shared__ float2 s_rv[NT_*A_];         // per-(type,atom): rj, (is_h ? -1 : vol)
    __shared__ unsigned char s_pd[A_*A_];   // path distances for this block type
    __shared__ int    s_ndon, s_nacc;
    __shared__ int    s_donHs[MD_], s_dhvys[MD_], s_accs[MA_], s_hybs[MA_];
    __shared__ float  s_wgp[2], s_lkgp[3], s_tors[6];   // sp2, sp3, ring
    __shared__ float4 s_xyz[JCHUNK_];       // staged j atoms: x,y,z,rj (H -> -1e6 sentinel)
    __shared__ float  s_vol[JCHUNK_];
    __shared__ double s_red[NW_][2];

    int cta = blockIdx.x;
    int c   = cta % CH_;
    int pb  = cta / CH_;
    int p   = pb / B_;
    int b   = pb - p*B_;
    int tid = threadIdx.x;
    int bt  = btype[p*B_+b];
    const float* cblk = coords + (size_t)(p*N_ + b*A_)*3;
    const float4* lkp4 = (const float4*)lkp;

    // ---- phase 0: ONE coalesced prefetch burst (all independent LDGs) ----
    if (tid < B_) {
        s_sepok[tid] = (minsep[(p*B_+b)*B_+tid] >= 4) ? 1 : 0;
        s_bt[tid]    = (short)btype[p*B_+tid];
    } else if (tid < B_+A_) {
        int a = tid - B_;
        s_rng0[a]   = ranges[(bt*A_+a)*2];
        s_b1[a]     = bonds [(bt*A_+a)*2+1];
        s_lkprow[a] = lkp4[bt*A_+a];
    } else if (tid < B_+A_+A_*3) {
        int t = tid - (B_+A_);
        s_cb[t] = cblk[t];
    } else {
        int t = tid - (B_+A_+A_*3);        // 0..31
        if      (t == 0)  s_ndon = n_donH[bt];
        else if (t == 1)  s_nacc = n_acc[bt];
        else if (t < 6)   s_donHs[t-2]  = donH_i[bt*MD_+t-2];
        else if (t < 10)  s_dhvys[t-6]  = don_hvy_i[bt*MD_+t-6];
        else if (t < 14)  s_accs[t-10]  = acc_i_arr[bt*MA_+t-10];
        else if (t < 18)  s_hybs[t-14]  = hyb_arr[bt*MA_+t-14];
        else if (t < 20)  s_wgp[t-18]   = wgp[t-18];
        else if (t < 23)  s_lkgp[t-20]  = lkgp[t-20];
        else if (t < 25)  s_tors[t-23]  = sp2t[t-23];
        else if (t < 27)  s_tors[2+t-25]= sp3t[t-25];
        else if (t < 29)  s_tors[4+t-27]= ringt[t-27];
    }
    for (int e = tid; e < NT_*A_; e += TPB_) {
        float4 q = lkp4[e];
        s_rv[e] = make_float2(q.x, (is_h[e] != 0) ? -1.f : q.w);
    }
    for (int i = tid; i < A_*A_; i += TPB_)
        s_pd[i] = (unsigned char)max(0, min(pathd[bt*A_*A_+i], 255));
    __syncthreads();

    int warp  = tid >> 5;
    int lane  = tid & 31;
    int jbase = c*JCHUNK_;

    // ---- phase 1 (per-warp, no CTA barrier inside) ----
    // (a) stage this warp's 128 j atoms
    {
        const float* cp = coords + (size_t)p*N_*3;
        #pragma unroll
        for (int it = 0; it < 4; it++) {
            int idx = warp*JPW_ + it*32 + lane;
            int j   = jbase + idx;
            int bj  = j >> 5;
            int a   = j & 31;
            int btj = s_bt[bj];
            float2 rv = s_rv[btj*A_+a];
            float x = cp[3*j], y = cp[3*j+1], z = cp[3*j+2];
            bool hyd = (rv.y < 0.f);
            s_xyz[idx] = hyd ? make_float4(-1e6f,-1e6f,-1e6f,0.f)
                             : make_float4(x, y, z, rv.x);
            s_vol[idx] = hyd ? 0.f : rv.y;
        }
    }
    // (b) lane 0 computes water for slot==warp (all-LDS, short chain)
    int slot = warp;
    int arow = 0;
    if (lane == 0) {
        float wdist = s_wgp[0], wang = s_wgp[1];
        int ai = 0;
        float4 POL = make_float4(1e6f,1e6f,1e6f,0.f);
        float4 W0  = make_float4(0.f,0.f,0.f,0.f);
        float4 W1  = make_float4(0.f,0.f,0.f,1.f);
        if (slot < MD_) {                      // donor slot
            if (slot < s_ndon) {
                ai      = clampA(s_dhvys[slot]);
                int hi  = clampA(s_donHs[slot]);
                float hx=s_cb[ai*3], hy=s_cb[ai*3+1], hz=s_cb[ai*3+2];
                float Hx=s_cb[hi*3], Hy=s_cb[hi*3+1], Hz=s_cb[hi*3+2];
                float dx=Hx-hx, dy=Hy-hy, dz=Hz-hz;
                float inv = rsqrtf(dx*dx+dy*dy+dz*dz + 1e-12f);
                float4 q = s_lkprow[ai];       // ri,dgi,lam,vol
                POL = make_float4(hx, hy, hz, q.x);
                W0  = make_float4(hx+wdist*inv*dx, hy+wdist*inv*dy, hz+wdist*inv*dz,
                                  C_LK*q.y/q.z);
                W1  = make_float4(1e5f, 1e5f, 1e5f, 1.0f/q.z);  // masked water -> far
            }
        } else {                               // acceptor slot
            int i = slot - MD_;
            if (i < s_nacc) {
                ai        = clampA(s_accs[i]);
                int r0    = clampA(s_rng0[ai]);
                int base  = clampA(s_b1[r0]);
                int r1    = clampA(s_rng0[base]);
                int base2 = clampA(s_b1[r1]);
                float cx=s_cb[ai*3],   cy=s_cb[ai*3+1],   cz=s_cb[ai*3+2];
                float bx=s_cb[base*3], by=s_cb[base*3+1], bz=s_cb[base*3+2];
                float ax=s_cb[base2*3],ay=s_cb[base2*3+1],az=s_cb[base2*3+2];
                float e1x=cx-bx, e1y=cy-by, e1z=cz-bz;
                float inv = rsqrtf(e1x*e1x+e1y*e1y+e1z*e1z + 1e-12f);
                e1x*=inv; e1y*=inv; e1z*=inv;
                float ux=bx-ax, uy=by-ay, uz=bz-az;
                float nx=uy*e1z-uz*e1y, ny=uz*e1x-ux*e1z, nz=ux*e1y-uy*e1x;
                inv = rsqrtf(nx*nx+ny*ny+nz*nz + 1e-12f);
                nx*=inv; ny*=inv; nz*=inv;
                float e2x=ny*e1z-nz*e1y, e2y=nz*e1x-nx*e1z, e2z=nx*e1y-ny*e1x;
                int hyb = s_hybs[i];
                float chi0 = s_tors[hyb*2], chi1 = s_tors[hyb*2+1];
                float ct=cosf(wang), st=sinf(wang);
                float a1 = -wdist*ct;
                float b0 = wdist*st*cosf(chi0), c0 = wdist*st*sinf(chi0);
                float b1 = wdist*st*cosf(chi1), c1 = wdist*st*sinf(chi1);
                float4 q = s_lkprow[ai];
                POL = make_float4(cx, cy, cz, q.x);
                W0  = make_float4(cx + a1*e1x + b0*e2x + c0*nx,
                                  cy + a1*e1y + b0*e2y + c0*ny,
                                  cz + a1*e1z + b0*e2z + c0*nz,
                                  C_LK*q.y/q.z);
                W1  = make_float4(cx + a1*e1x + b1*e2x + c1*nx,
                                  cy + a1*e1y + b1*e2y + c1*ny,
                                  cz + a1*e1z + b1*e2z + c1*nz,
                                  1.0f/q.z);
            }
        }
        s_pol[slot] = POL;
        s_w0[slot]  = W0;
        s_w1[slot]  = W1;
        arow = ai*A_;
    }
    // (c) pmask for slot==warp via smem-fed ballot
    arow = __shfl_sync(FULLM, arow, 0);
    unsigned mk = __ballot_sync(FULLM, s_pd[arow + lane] >= 4);
    if (lane == 0) s_pmask[slot] = mk;
    __syncthreads();

    // ---- phase 2: scan + dense batches ----
    float px[NPOL_], py[NPOL_], pz[NPOL_];
    #pragma unroll
    for (int k = 0; k < NPOL_; k++) {
        float4 q = s_pol[k];
        px[k]=q.x; py[k]=q.y; pz[k]=q.z;
    }
    float cutoff2 = s_lkgp[0]*s_lkgp[0];
    float ramp2   = s_lkgp[1];
    float d2lr    = s_lkgp[2] + ramp2;
    float invramp = 1.0f/ramp2;

    // phase A: straight-line scan of this thread's 4 atoms x 8 polars
    unsigned mymask = 0;
    #pragma unroll
    for (int it = 0; it < 4; it++) {
        int i = warp*JPW_ + it*32 + lane;
        float4 aj = s_xyz[i];               // LDS.128 (H -> far sentinel)
        #pragma unroll
        for (int k = 0; k < NPOL_; k++) {
            float dx = px[k]-aj.x, dy = py[k]-aj.y, dz = pz[k]-aj.z;
            float d2 = dx*dx + dy*dy + dz*dz;
            mymask |= (d2 < cutoff2) ? (1u << (it*NPOL_ + k)) : 0u;
        }
    }

    // phase B: warp-wide compaction, then dense batches of 32 pairs
    int nmine = __popc(mymask);
    int pre = nmine;                        // inclusive scan
    #pragma unroll
    for (int off = 1; off < 32; off <<= 1) {
        int v = __shfl_up_sync(FULLM, pre, off);
        if (lane >= off) pre += v;
    }
    int total = __shfl_sync(FULLM, pre, 31);
    int excl  = pre - nmine;                // exclusive prefix for this lane

    float sum0 = 0.f, sum1 = 0.f;
    for (int base = 0; base < total; base += 32) {
        int t = base + lane;
        bool valid = (t < total);
        // binary-search the source lane: largest L with excl[L] <= t
        int L = 0;
        #pragma unroll
        for (int step = 16; step >= 1; step >>= 1) {
            int cand = L + step;
            int e = __shfl_sync(FULLM, excl, cand & 31);
            if (cand < 32 && e <= t) L = cand;
        }
        unsigned srcmask = __shfl_sync(FULLM, mymask, L);
        int eL           = __shfl_sync(FULLM, excl,  L);
        int off  = t - eL;                  // 0..popc-1 when valid
        int bit  = valid ? (int)__fns(srcmask, 0, off + 1) : 0;
        int itid = bit >> 3, k = bit & 7;
        int i    = warp*JPW_ + itid*32 + L;
        if (!valid) i = warp*JPW_;
        // heavy body (dense lanes)
        float4 aj  = s_xyz[i];
        float  vol = s_vol[i];
        float4 pol = s_pol[k];
        float4 w0  = s_w0[k];
        float4 w1  = s_w1[k];
        int j   = jbase + i;
        int bj  = j >> 5;
        int ajA = j & 31;
        float g;
        if (bj == b) g = (float)((s_pmask[k] >> ajA) & 1u);
        else         g = (s_sepok[bj] != 0) ? 1.f : 0.f;
        if (!valid)  g = 0.f;
        float dx = pol.x-aj.x, dy = pol.y-aj.y, dz = pol.z-aj.z;
        float d2c = fmaxf(dx*dx + dy*dy + dz*dz, 0.01f);
        float rin = rsqrtf(d2c);            // 1/d
        float d   = d2c * rin;              // d
        float xq  = (d - pol.w - aj.w) * w1.w;
        float lk  = g * (w0.w * vol * __expf(-xq*xq)) * (rin*rin);
        float a0x=w0.x-aj.x, a0y=w0.y-aj.y, a0z=w0.z-aj.z;
        float dw0 = a0x*a0x + a0y*a0y + a0z*a0z;
        float a1x=w1.x-aj.x, a1y=w1.y-aj.y, a1z=w1.z-aj.z;
        float dw1 = a1x*a1x + a1y*a1y + a1z*a1z;
        float dm = fminf(dw0, dw1);
        float wt = __saturatef((d2lr - dm) * invramp);
        float fr = wt*wt*(3.f - 2.f*wt);
        sum0 += lk;
        sum1 += lk*fr;
    }

    // deterministic CTA reduction (fp64)
    double d0 = sum0, d1 = sum1;
    for (int off = 16; off; off >>= 1) {
        d0 += __shfl_xor_sync(FULLM, d0, off);
        d1 += __shfl_xor_sync(FULLM, d1, off);
    }
    if (lane == 0) { s_red[warp][0]=d0; s_red[warp][1]=d1; }
    __syncthreads();
    if (tid == 0) {
        double a=0, cc=0;
        #pragma unroll
        for (int w = 0; w < NW_; w++) { a+=s_red[w][0]; cc+=s_red[w][1]; }
        g_partial[cta*2]   = a;
        g_partial[cta*2+1] = cc;
    }

    // ---- last-CTA final reduce (fixed-order -> deterministic) ----
    __shared__ bool s_last;
    __threadfence();
    if (tid == 0)
        s_last = (atomicAdd(&g_done, 1u) == (unsigned)(gridDim.x - 1));
    __syncthreads();
    if (!s_last) return;

    __shared__ double rr0[TPB_], rr1[TPB_];
    for (int pp = 0; pp < P_; pp++) {
        double a = 0, cc = 0;
        for (int i = tid; i < B_*CH_; i += TPB_) {
            a  += g_partial[(pp*B_*CH_+i)*2];
            cc += g_partial[(pp*B_*CH_+i)*2+1];
        }
        rr0[tid] = a; rr1[tid] = cc;
        __syncthreads();
        for (int s = TPB_/2; s >= 1; s >>= 1) {
            if (tid < s) { rr0[tid] += rr0[tid+s]; rr1[tid] += rr1[tid+s]; }
            __syncthreads();
        }
        if (tid == 0) {
            out[pp]     = (float)rr0[0];
            out[P_+pp]  = (float)rr1[0];
        }
        __syncthreads();
    }
    if (tid == 0) g_done = 0;            // reset for next graph replay
}

extern "C" void kernel_launch(void* const* d_in, const int* in_sizes, int n_in,
                              void* d_out, int out_size) {
    const float* coords  = (const float*)d_in[0];
    const int*   btype   = (const int*)  d_in[1];
    const int*   minsep  = (const int*)  d_in[2];
    // d_in[3] = bt_n_atoms (unused: all blocks have A_ atoms)
    const int*   bonds   = (const int*)  d_in[4];
    const int*   ranges  = (const int*)  d_in[5];
    const int*   n_donH  = (const int*)  d_in[6];
    const int*   n_acc   = (const int*)  d_in[7];
    const int*   donH_i  = (const int*)  d_in[8];
    const int*   don_hvy = (const int*)  d_in[9];
    const int*   acc_i   = (const int*)  d_in[10];
    const int*   hyb     = (const int*)  d_in[11];
    const int*   is_h    = (const int*)  d_in[12];
    const float* lkp     = (const float*)d_in[13];
    const int*   pathd   = (const int*)  d_in[14];
    const float* lkgp    = (const float*)d_in[15];
    const float* wgp     = (const float*)d_in[16];
    const float* sp2     = (const float*)d_in[17];
    const float* sp3     = (const float*)d_in[18];
    const float* ringt   = (const float*)d_in[19];

    lkball_kernel<<<P_*B_*CH_, TPB_>>>(coords, btype, minsep, bonds, ranges,
                                       n_donH, n_acc, donH_i, don_hvy, acc_i, hyb,
                                       lkp, is_h, pathd, lkgp, wgp, sp2, sp3, ringt,
                                       (float*)d_out);
}

// round 15
// speedup vs baseline: 1.0710x; 1.0710x over previous
#include <cuda_runtime.h>

#define P_ 2
#define B_ 96
#define A_ 32
#define N_ 3072        // B_*A_
#define NT_ 24
#define MD_ 4
#define MA_ 4
#define NPOL_ 8
#define CH_ 2          // j-range chunks per (pose,block)
#define TPB_ 256
#define NW_ (TPB_/32)
#define JCHUNK_ (N_/CH_)       // 1536 j atoms per CTA
#define STG_ 224               // staging threads (warps 0-6)
#define C_LK 0.0897935610625833f
#define FULLM 0xffffffffu

// Scratch (no allocations allowed)
__device__ double g_partial[P_*B_*CH_*2];
__device__ unsigned int g_done;   // zero-init; last CTA resets -> graph-replay safe

__device__ __forceinline__ int clampA(int v){ return min(max(v,0), A_-1); }

typedef unsigned long long ull;
__device__ __forceinline__ ull pack2(float lo, float hi){
    ull r; asm("mov.b64 %0, {%1, %2};" : "=l"(r) : "f"(lo), "f"(hi)); return r;
}
__device__ __forceinline__ ull add2(ull a, ull b){
    ull r; asm("add.rn.f32x2 %0, %1, %2;" : "=l"(r) : "l"(a), "l"(b)); return r;
}
__device__ __forceinline__ ull mul2(ull a, ull b){
    ull r; asm("mul.rn.f32x2 %0, %1, %2;" : "=l"(r) : "l"(a), "l"(b)); return r;
}
__device__ __forceinline__ ull fma2(ull a, ull b, ull c){
    ull r; asm("fma.rn.f32x2 %0, %1, %2, %3;" : "=l"(r) : "l"(a), "l"(b), "l"(c)); return r;
}
__device__ __forceinline__ void unpack2(ull v, float& lo, float& hi){
    asm("mov.b64 {%0, %1}, %2;" : "=f"(lo), "=f"(hi) : "l"(v));
}

__global__ void __launch_bounds__(TPB_, 3) lkball_kernel(
    const float* __restrict__ coords,
    const int*   __restrict__ btype,
    const int*   __restrict__ minsep,
    const int*   __restrict__ bonds,     // (NT,A,2)
    const int*   __restrict__ ranges,    // (NT,A,2)
    const int*   __restrict__ n_donH,
    const int*   __restrict__ n_acc,
    const int*   __restrict__ donH_i,
    const int*   __restrict__ don_hvy_i,
    const int*   __restrict__ acc_i_arr,
    const int*   __restrict__ hyb_arr,
    const float* __restrict__ lkp,       // (NT,A,4) -> float4 aligned
    const int*   __restrict__ is_h,      // (NT,A)
    const int*   __restrict__ pathd,     // (NT,A,A)
    const float* __restrict__ lkgp,
    const float* __restrict__ wgp,
    const float* __restrict__ sp2t,
    const float* __restrict__ sp3t,
    const float* __restrict__ ringt,
    float*       __restrict__ out)
{
    __shared__ float4 st_pol[NPOL_], st_w0[NPOL_], st_w1[NPOL_];
    __shared__ int    st_a[NPOL_], st_act[NPOL_];
    __shared__ float4 s_pol[NPOL_], s_w0[NPOL_], s_w1[NPOL_];
    __shared__ int    s_arow[NPOL_];
    __shared__ unsigned s_pmask[NPOL_];     // same-block sep>=4 bit per atom-in-block
    __shared__ unsigned char s_sepok[B_];
    __shared__ short  s_bt[B_];
    __shared__ int    s_rng0[A_], s_b1[A_]; // this block-type's ranges[...,0], bonds[...,1]
    __shared__ float  s_cb[A_*3];           // this block's coords
    __shared__ float4 s_xyz[JCHUNK_];       // staged j atoms: x,y,z,rj (H -> -1e6 sentinel)
    __shared__ float  s_vol[JCHUNK_];
    __shared__ double s_red[NW_][2];

    int cta = blockIdx.x;
    int c   = cta % CH_;
    int pb  = cta / CH_;
    int p   = pb / B_;
    int b   = pb - p*B_;
    int tid = threadIdx.x;
    int bt  = btype[p*B_+b];
    const float* cblk = coords + (size_t)(p*N_ + b*A_)*3;
    const float4* lkp4 = (const float4*)lkp;

    // ---- phase 0: coalesced prefetch of per-block tables (all independent LDGs)
    if (tid < B_) {
        s_sepok[tid] = (minsep[(p*B_+b)*B_+tid] >= 4) ? 1 : 0;
        s_bt[tid]    = (short)btype[p*B_+tid];
    }
    if (tid < A_) {
        s_rng0[tid] = ranges[(bt*A_+tid)*2];
        s_b1[tid]   = bonds [(bt*A_+tid)*2+1];
    }
    if (tid >= 128 && tid < 128 + A_*3) {
        s_cb[tid-128] = cblk[tid-128];
    }
    __syncthreads();

    // ---- phase 1: warp 7 does water generation (smem-fed, short chain)
    //               warps 0-6 stage the j range concurrently
    if (tid >= STG_) {
        int slot = tid - STG_;
        if (slot < NPOL_) {
            float wdist = wgp[0], wang = wgp[1];
            int active = 0, ai = 0;
            float xp0=0,xp1=0,xp2=0,w00=0,w01=0,w02=0,w10=0,w11=0,w12=0;
            if (slot < MD_) {                      // donor slot
                if (slot < n_donH[bt]) {
                    active = 1;
                    ai      = clampA(don_hvy_i[bt*MD_+slot]);
                    int hi  = clampA(donH_i[bt*MD_+slot]);
                    float hx=s_cb[ai*3], hy=s_cb[ai*3+1], hz=s_cb[ai*3+2];
                    float Hx=s_cb[hi*3], Hy=s_cb[hi*3+1], Hz=s_cb[hi*3+2];
                    float dx=Hx-hx, dy=Hy-hy, dz=Hz-hz;
                    float inv = rsqrtf(dx*dx+dy*dy+dz*dz + 1e-12f);
                    xp0=hx; xp1=hy; xp2=hz;
                    w00=hx+wdist*inv*dx; w01=hy+wdist*inv*dy; w02=hz+wdist*inv*dz;
                    w10=1e5f; w11=1e5f; w12=1e5f;  // masked water -> far sentinel
                }
            } else {                               // acceptor slot
                int i = slot - MD_;
                if (i < n_acc[bt]) {
                    active = 1;
                    ai        = clampA(acc_i_arr[bt*MA_+i]);
                    int r0    = clampA(s_rng0[ai]);
                    int base  = clampA(s_b1[r0]);
                    int r1    = clampA(s_rng0[base]);
                    int base2 = clampA(s_b1[r1]);
                    float cx=s_cb[ai*3],   cy=s_cb[ai*3+1],   cz=s_cb[ai*3+2];
                    float bx=s_cb[base*3], by=s_cb[base*3+1], bz=s_cb[base*3+2];
                    float ax=s_cb[base2*3],ay=s_cb[base2*3+1],az=s_cb[base2*3+2];
                    float e1x=cx-bx, e1y=cy-by, e1z=cz-bz;
                    float inv = rsqrtf(e1x*e1x+e1y*e1y+e1z*e1z + 1e-12f);
                    e1x*=inv; e1y*=inv; e1z*=inv;
                    float ux=bx-ax, uy=by-ay, uz=bz-az;
                    float nx=uy*e1z-uz*e1y, ny=uz*e1x-ux*e1z, nz=ux*e1y-uy*e1x;
                    inv = rsqrtf(nx*nx+ny*ny+nz*nz + 1e-12f);
                    nx*=inv; ny*=inv; nz*=inv;
                    float e2x=ny*e1z-nz*e1y, e2y=nz*e1x-nx*e1z, e2z=nx*e1y-ny*e1x;
                    int hyb = hyb_arr[bt*MA_+i];
                    float chi0, chi1;
                    if      (hyb == 0) { chi0=sp2t[0];  chi1=sp2t[1];  }
                    else if (hyb == 1) { chi0=sp3t[0];  chi1=sp3t[1];  }
                    else               { chi0=ringt[0]; chi1=ringt[1]; }
                    float ct=cosf(wang), st=sinf(wang);
                    float a1 = -wdist*ct;
                    float b0 = wdist*st*cosf(chi0), c0 = wdist*st*sinf(chi0);
                    float b1 = wdist*st*cosf(chi1), c1 = wdist*st*sinf(chi1);
                    xp0=cx; xp1=cy; xp2=cz;
                    w00 = cx + a1*e1x + b0*e2x + c0*nx;
                    w01 = cy + a1*e1y + b0*e2y + c0*ny;
                    w02 = cz + a1*e1z + b0*e2z + c0*nz;
                    w10 = cx + a1*e1x + b1*e2x + c1*nx;
                    w11 = cy + a1*e1y + b1*e2y + c1*ny;
                    w12 = cz + a1*e1z + b1*e2z + c1*nz;
                }
            }
            st_act[slot] = active;
            if (active) {
                float4 q = lkp4[bt*A_+ai];         // ri,dgi,lam,vol
                st_pol[slot] = make_float4(xp0, xp1, xp2, q.x);
                st_w0[slot]  = make_float4(w00, w01, w02, C_LK*q.y/q.z);
                st_w1[slot]  = make_float4(w10, w11, w12, 1.0f/q.z);
                st_a[slot]   = ai*A_;
            }
        }
    } else {
        // stage this CTA's j range: coords+rj (H -> far sentinel), vol
        int jb = c*JCHUNK_;
        const float* cp = coords + (size_t)p*N_*3;
        for (int i = tid; i < JCHUNK_; i += STG_) {
            int j   = jb + i;
            int bj  = j >> 5;
            int a   = j & 31;
            int btj = s_bt[bj];
            float4 q = lkp4[btj*A_+a];
            bool hyd = (is_h[btj*A_+a] != 0);
            float x = cp[3*j], y = cp[3*j+1], z = cp[3*j+2];
            s_xyz[i] = hyd ? make_float4(-1e6f,-1e6f,-1e6f,0.f)
                           : make_float4(x, y, z, q.x);
            s_vol[i] = hyd ? 0.f : q.w;
        }
    }
    __syncthreads();
    if (tid == 0) {                         // compact + pad to 8 with dummies
        int n = 0;
        for (int t = 0; t < NPOL_; t++) if (st_act[t]) {
            s_pol[n]=st_pol[t]; s_w0[n]=st_w0[t]; s_w1[n]=st_w1[t]; s_arow[n]=st_a[t];
            n++;
        }
        for (; n < NPOL_; n++) {
            s_pol[n]=make_float4(1e6f,1e6f,1e6f,0.f);   // never passes cutoff
            s_w0[n]=make_float4(0,0,0,0); s_w1[n]=make_float4(0,0,0,1.f);
            s_arow[n]=0;
        }
    }
    __syncthreads();
    // same-block separation bitmasks: warp k -> pol k, lane a -> atom a
    if (tid < NPOL_*32) {
        int k = tid >> 5, a = tid & 31;
        unsigned mk = __ballot_sync(FULLM, pathd[bt*A_*A_ + s_arow[k] + a] >= 4);
        if (a == 0) s_pmask[k] = mk;
    }
    __syncthreads();

    // packed-duplicate polar coords in registers (f32x2 lanes {p,p})
    ull PX2[NPOL_], PY2[NPOL_], PZ2[NPOL_];
    #pragma unroll
    for (int k = 0; k < NPOL_; k++) {
        float4 q = s_pol[k];
        PX2[k] = pack2(q.x, q.x);
        PY2[k] = pack2(q.y, q.y);
        PZ2[k] = pack2(q.z, q.z);
    }

    float cutoff2 = lkgp[0]*lkgp[0];
    float ramp2   = lkgp[1];
    float d2lr    = lkgp[2] + ramp2;
    float invramp = 1.0f/ramp2;

    int jbase = c*JCHUNK_;
    int warp  = tid >> 5;
    int lane  = tid & 31;

    float sum0 = 0.f, sum1 = 0.f;
    #pragma unroll
    for (int pr = 0; pr < JCHUNK_/(2*TPB_); pr++) {
        int i0 = pr*2*TPB_ + tid;
        int i1 = i0 + TPB_;
        float4 a0 = s_xyz[i0];              // two independent LDS.128
        float4 a1 = s_xyz[i1];
        ull NAX = pack2(-a0.x, -a1.x);
        ull NAY = pack2(-a0.y, -a1.y);
        ull NAZ = pack2(-a0.z, -a1.z);
        unsigned bits0 = 0, bits1 = 0;
        #pragma unroll
        for (int k = 0; k < NPOL_; k++) {
            ull dx = add2(PX2[k], NAX);
            ull dy = add2(PY2[k], NAY);
            ull dz = add2(PZ2[k], NAZ);
            ull s  = fma2(dz, dz, fma2(dy, dy, mul2(dx, dx)));
            float q0, q1; unpack2(s, q0, q1);
            bits0 |= (q0 < cutoff2) ? (1u << k) : 0u;
            bits1 |= (q1 < cutoff2) ? (1u << k) : 0u;
        }
        #pragma unroll
        for (int half = 0; half < 2; half++) {
            unsigned bits = half ? bits1 : bits0;
            float4  aj    = half ? a1 : a0;
            int     i     = half ? i1 : i0;
            if (bits) {                      // single divergent region per atom
                // warp-uniform block identity: all lanes share (i>>5); ajA==lane
                int bjH = (jbase + pr*2*TPB_ + half*TPB_ + warp*32) >> 5;
                bool same = (bjH == b);
                float okI = (s_sepok[bjH] != 0) ? 1.f : 0.f;
                float vol = s_vol[i];
                do {                         // ~1-2 iterations per lane
                    int k = __ffs(bits) - 1;
                    bits &= bits - 1u;
                    float4 pol = s_pol[k];
                    float4 w0  = s_w0[k];
                    float4 w1  = s_w1[k];
                    float g = same ? (float)((s_pmask[k] >> lane) & 1u) : okI;
                    float dx = pol.x-aj.x, dy = pol.y-aj.y, dz = pol.z-aj.z;
                    float d2c = fmaxf(dx*dx + dy*dy + dz*dz, 0.01f);
                    float rin = rsqrtf(d2c);            // 1/d
                    float d   = d2c * rin;              // d
                    float xq  = (d - pol.w - aj.w) * w1.w;
                    float lk  = g * (w0.w * vol * __expf(-xq*xq)) * (rin*rin);
                    float a0x=w0.x-aj.x, a0y=w0.y-aj.y, a0z=w0.z-aj.z;
                    float dw0 = a0x*a0x + a0y*a0y + a0z*a0z;
                    float a1x=w1.x-aj.x, a1y=w1.y-aj.y, a1z=w1.z-aj.z;
                    float dw1 = a1x*a1x + a1y*a1y + a1z*a1z;
                    float dm = fminf(dw0, dw1);
                    float wt = __saturatef((d2lr - dm) * invramp);
                    float fr = wt*wt*(3.f - 2.f*wt);
                    sum0 += lk;
                    sum1 += lk*fr;
                } while (bits);
            }
        }
    }

    // deterministic CTA reduction (fp64)
    double d0 = sum0, d1 = sum1;
    for (int off = 16; off; off >>= 1) {
        d0 += __shfl_xor_sync(FULLM, d0, off);
        d1 += __shfl_xor_sync(FULLM, d1, off);
    }
    if (lane == 0) { s_red[warp][0]=d0; s_red[warp][1]=d1; }
    __syncthreads();
    if (tid == 0) {
        double a=0, cc=0;
        #pragma unroll
        for (int w = 0; w < NW_; w++) { a+=s_red[w][0]; cc+=s_red[w][1]; }
        g_partial[cta*2]   = a;
        g_partial[cta*2+1] = cc;
    }

    // ---- last-CTA final reduce (fixed-order -> deterministic) ----
    __shared__ bool s_last;
    __threadfence();
    if (tid == 0)
        s_last = (atomicAdd(&g_done, 1u) == (unsigned)(gridDim.x - 1));
    __syncthreads();
    if (!s_last) return;

    __shared__ double rr0[TPB_], rr1[TPB_];
    for (int pp = 0; pp < P_; pp++) {
        double a = 0, cc = 0;
        for (int i = tid; i < B_*CH_; i += TPB_) {
            a  += g_partial[(pp*B_*CH_+i)*2];
            cc += g_partial[(pp*B_*CH_+i)*2+1];
        }
        rr0[tid] = a; rr1[tid] = cc;
        __syncthreads();
        for (int s = TPB_/2; s >= 1; s >>= 1) {
            if (tid < s) { rr0[tid] += rr0[tid+s]; rr1[tid] += rr1[tid+s]; }
            __syncthreads();
        }
        if (tid == 0) {
            out[pp]     = (float)rr0[0];
            out[P_+pp]  = (float)rr1[0];
        }
        __syncthreads();
    }
    if (tid == 0) g_done = 0;            // reset for next graph replay
}

extern "C" void kernel_launch(void* const* d_in, const int* in_sizes, int n_in,
                              void* d_out, int out_size) {
    const float* coords  = (const float*)d_in[0];
    const int*   btype   = (const int*)  d_in[1];
    const int*   minsep  = (const int*)  d_in[2];
    // d_in[3] = bt_n_atoms (unused: all blocks have A_ atoms)
    const int*   bonds   = (const int*)  d_in[4];
    const int*   ranges  = (const int*)  d_in[5];
    const int*   n_donH  = (const int*)  d_in[6];
    const int*   n_acc   = (const int*)  d_in[7];
    const int*   donH_i  = (const int*)  d_in[8];
    const int*   don_hvy = (const int*)  d_in[9];
    const int*   acc_i   = (const int*)  d_in[10];
    const int*   hyb     = (const int*)  d_in[11];
    const int*   is_h    = (const int*)  d_in[12];
    const float* lkp     = (const float*)d_in[13];
    const int*   pathd   = (const int*)  d_in[14];
    const float* lkgp    = (const float*)d_in[15];
    const float* wgp     = (const float*)d_in[16];
    const float* sp2     = (const float*)d_in[17];
    const float* sp3     = (const float*)d_in[18];
    const float* ringt   = (const float*)d_in[19];

    lkball_kernel<<<P_*B_*CH_, TPB_>>>(coords, btype, minsep, bonds, ranges,
                                       n_donH, n_acc, donH_i, don_hvy, acc_i, hyb,
                                       lkp, is_h, pathd, lkgp, wgp, sp2, sp3, ringt,
                                       (float*)d_out);
}

// round 16
// speedup vs baseline: 1.0808x; 1.0091x over previous
#include <cuda_runtime.h>

#define P_ 2
#define B_ 96
#define A_ 32
#define N_ 3072        // B_*A_
#define NT_ 24
#define MD_ 4
#define MA_ 4
#define NPOL_ 8
#define CH_ 2          // j-range chunks per (pose,block)
#define TPB_ 256
#define NW_ (TPB_/32)
#define JCHUNK_ (N_/CH_)       // 1536 j atoms per CTA
#define STG_ 224               // staging threads (warps 0-6)
#define C_LK 0.0897935610625833f
#define FULLM 0xffffffffu

// Scratch (no allocations allowed)
__device__ double g_partial[P_*B_*CH_*2];
__device__ unsigned int g_done;   // zero-init; last CTA resets -> graph-replay safe

__device__ __forceinline__ int clampA(int v){ return min(max(v,0), A_-1); }

typedef unsigned long long ull;
__device__ __forceinline__ ull pack2(float lo, float hi){
    ull r; asm("mov.b64 %0, {%1, %2};" : "=l"(r) : "f"(lo), "f"(hi)); return r;
}
__device__ __forceinline__ ull add2(ull a, ull b){
    ull r; asm("add.rn.f32x2 %0, %1, %2;" : "=l"(r) : "l"(a), "l"(b)); return r;
}
__device__ __forceinline__ ull mul2(ull a, ull b){
    ull r; asm("mul.rn.f32x2 %0, %1, %2;" : "=l"(r) : "l"(a), "l"(b)); return r;
}
__device__ __forceinline__ ull fma2(ull a, ull b, ull c){
    ull r; asm("fma.rn.f32x2 %0, %1, %2, %3;" : "=l"(r) : "l"(a), "l"(b), "l"(c)); return r;
}
__device__ __forceinline__ void unpack2(ull v, float& lo, float& hi){
    asm("mov.b64 {%0, %1}, %2;" : "=f"(lo), "=f"(hi) : "l"(v));
}

// phase-2 main loop specialized on active polar-slot count bucket NP
template<int NP>
__device__ __forceinline__ void scan_phase(
    const float4* __restrict__ s_pol, const float4* __restrict__ s_w0,
    const float4* __restrict__ s_w1,  const unsigned* __restrict__ s_pmask,
    const unsigned char* __restrict__ s_sepok,
    const float4* __restrict__ s_xyz, const float* __restrict__ s_vol,
    int b, int jbase, int warp, int lane,
    float cutoff2, float d2lr, float invramp, int tid,
    float& sum0, float& sum1)
{
    // packed-duplicate polar coords in registers (f32x2 lanes {p,p})
    ull PX2[NP], PY2[NP], PZ2[NP];
    #pragma unroll
    for (int k = 0; k < NP; k++) {
        float4 q = s_pol[k];
        PX2[k] = pack2(q.x, q.x);
        PY2[k] = pack2(q.y, q.y);
        PZ2[k] = pack2(q.z, q.z);
    }
    #pragma unroll
    for (int pr = 0; pr < JCHUNK_/(2*TPB_); pr++) {
        int i0 = pr*2*TPB_ + tid;
        int i1 = i0 + TPB_;
        float4 a0 = s_xyz[i0];              // two independent LDS.128
        float4 a1 = s_xyz[i1];
        ull NAX = pack2(-a0.x, -a1.x);
        ull NAY = pack2(-a0.y, -a1.y);
        ull NAZ = pack2(-a0.z, -a1.z);
        unsigned bits0 = 0, bits1 = 0;
        #pragma unroll
        for (int k = 0; k < NP; k++) {
            ull dx = add2(PX2[k], NAX);
            ull dy = add2(PY2[k], NAY);
            ull dz = add2(PZ2[k], NAZ);
            ull s  = fma2(dz, dz, fma2(dy, dy, mul2(dx, dx)));
            float q0, q1; unpack2(s, q0, q1);
            bits0 |= (q0 < cutoff2) ? (1u << k) : 0u;
            bits1 |= (q1 < cutoff2) ? (1u << k) : 0u;
        }
        #pragma unroll
        for (int half = 0; half < 2; half++) {
            unsigned bits = half ? bits1 : bits0;
            float4  aj    = half ? a1 : a0;
            int     i     = half ? i1 : i0;
            if (bits) {                      // single divergent region per atom
                // warp-uniform block identity: all lanes share (i>>5); ajA==lane
                int bjH = (jbase + pr*2*TPB_ + half*TPB_ + warp*32) >> 5;
                bool same = (bjH == b);
                float okI = (s_sepok[bjH] != 0) ? 1.f : 0.f;
                float vol = s_vol[i];
                do {                         // ~1-2 iterations per lane
                    int k = __ffs(bits) - 1;
                    bits &= bits - 1u;
                    float4 pol = s_pol[k];
                    float4 w0  = s_w0[k];
                    float4 w1  = s_w1[k];
                    float g = same ? (float)((s_pmask[k] >> lane) & 1u) : okI;
                    float dx = pol.x-aj.x, dy = pol.y-aj.y, dz = pol.z-aj.z;
                    float d2c = fmaxf(dx*dx + dy*dy + dz*dz, 0.01f);
                    float rin = rsqrtf(d2c);            // 1/d
                    float d   = d2c * rin;              // d
                    float xq  = (d - pol.w - aj.w) * w1.w;
                    float lk  = g * (w0.w * vol * __expf(-xq*xq)) * (rin*rin);
                    float a0x=w0.x-aj.x, a0y=w0.y-aj.y, a0z=w0.z-aj.z;
                    float dw0 = a0x*a0x + a0y*a0y + a0z*a0z;
                    float a1x=w1.x-aj.x, a1y=w1.y-aj.y, a1z=w1.z-aj.z;
                    float dw1 = a1x*a1x + a1y*a1y + a1z*a1z;
                    float dm = fminf(dw0, dw1);
                    float wt = __saturatef((d2lr - dm) * invramp);
                    float fr = wt*wt*(3.f - 2.f*wt);
                    sum0 += lk;
                    sum1 += lk*fr;
                } while (bits);
            }
        }
    }
}

__global__ void __launch_bounds__(TPB_, 3) lkball_kernel(
    const float* __restrict__ coords,
    const int*   __restrict__ btype,
    const int*   __restrict__ minsep,
    const int*   __restrict__ bonds,     // (NT,A,2)
    const int*   __restrict__ ranges,    // (NT,A,2)
    const int*   __restrict__ n_donH,
    const int*   __restrict__ n_acc,
    const int*   __restrict__ donH_i,
    const int*   __restrict__ don_hvy_i,
    const int*   __restrict__ acc_i_arr,
    const int*   __restrict__ hyb_arr,
    const float* __restrict__ lkp,       // (NT,A,4) -> float4 aligned
    const int*   __restrict__ is_h,      // (NT,A)
    const int*   __restrict__ pathd,     // (NT,A,A)
    const float* __restrict__ lkgp,
    const float* __restrict__ wgp,
    const float* __restrict__ sp2t,
    const float* __restrict__ sp3t,
    const float* __restrict__ ringt,
    float*       __restrict__ out)
{
    __shared__ float4 st_pol[NPOL_], st_w0[NPOL_], st_w1[NPOL_];
    __shared__ int    st_a[NPOL_], st_act[NPOL_];
    __shared__ float4 s_pol[NPOL_], s_w0[NPOL_], s_w1[NPOL_];
    __shared__ int    s_arow[NPOL_];
    __shared__ int    s_npol;
    __shared__ unsigned s_pmask[NPOL_];     // same-block sep>=4 bit per atom-in-block
    __shared__ unsigned char s_sepok[B_];
    __shared__ short  s_bt[B_];
    __shared__ int    s_rng0[A_], s_b1[A_]; // this block-type's ranges[...,0], bonds[...,1]
    __shared__ float  s_cb[A_*3];           // this block's coords
    __shared__ float4 s_xyz[JCHUNK_];       // staged j atoms: x,y,z,rj (H -> -1e6 sentinel)
    __shared__ float  s_vol[JCHUNK_];
    __shared__ double s_red[NW_][2];

    int cta = blockIdx.x;
    int c   = cta % CH_;
    int pb  = cta / CH_;
    int p   = pb / B_;
    int b   = pb - p*B_;
    int tid = threadIdx.x;
    int bt  = btype[p*B_+b];
    const float* cblk = coords + (size_t)(p*N_ + b*A_)*3;
    const float4* lkp4 = (const float4*)lkp;

    // ---- phase 0: coalesced prefetch of per-block tables (all independent LDGs)
    if (tid < B_) {
        s_sepok[tid] = (minsep[(p*B_+b)*B_+tid] >= 4) ? 1 : 0;
        s_bt[tid]    = (short)btype[p*B_+tid];
    }
    if (tid < A_) {
        s_rng0[tid] = ranges[(bt*A_+tid)*2];
        s_b1[tid]   = bonds [(bt*A_+tid)*2+1];
    }
    if (tid >= 128 && tid < 128 + A_*3) {
        s_cb[tid-128] = cblk[tid-128];
    }
    __syncthreads();

    // ---- phase 1: warp 7 does water generation (smem-fed, short chain)
    //               warps 0-6 stage the j range concurrently
    if (tid >= STG_) {
        int slot = tid - STG_;
        if (slot < NPOL_) {
            float wdist = wgp[0], wang = wgp[1];
            int active = 0, ai = 0;
            float xp0=0,xp1=0,xp2=0,w00=0,w01=0,w02=0,w10=0,w11=0,w12=0;
            if (slot < MD_) {                      // donor slot
                if (slot < n_donH[bt]) {
                    active = 1;
                    ai      = clampA(don_hvy_i[bt*MD_+slot]);
                    int hi  = clampA(donH_i[bt*MD_+slot]);
                    float hx=s_cb[ai*3], hy=s_cb[ai*3+1], hz=s_cb[ai*3+2];
                    float Hx=s_cb[hi*3], Hy=s_cb[hi*3+1], Hz=s_cb[hi*3+2];
                    float dx=Hx-hx, dy=Hy-hy, dz=Hz-hz;
                    float inv = rsqrtf(dx*dx+dy*dy+dz*dz + 1e-12f);
                    xp0=hx; xp1=hy; xp2=hz;
                    w00=hx+wdist*inv*dx; w01=hy+wdist*inv*dy; w02=hz+wdist*inv*dz;
                    w10=1e5f; w11=1e5f; w12=1e5f;  // masked water -> far sentinel
                }
            } else {                               // acceptor slot
                int i = slot - MD_;
                if (i < n_acc[bt]) {
                    active = 1;
                    ai        = clampA(acc_i_arr[bt*MA_+i]);
                    int r0    = clampA(s_rng0[ai]);
                    int base  = clampA(s_b1[r0]);
                    int r1    = clampA(s_rng0[base]);
                    int base2 = clampA(s_b1[r1]);
                    float cx=s_cb[ai*3],   cy=s_cb[ai*3+1],   cz=s_cb[ai*3+2];
                    float bx=s_cb[base*3], by=s_cb[base*3+1], bz=s_cb[base*3+2];
                    float ax=s_cb[base2*3],ay=s_cb[base2*3+1],az=s_cb[base2*3+2];
                    float e1x=cx-bx, e1y=cy-by, e1z=cz-bz;
                    float inv = rsqrtf(e1x*e1x+e1y*e1y+e1z*e1z + 1e-12f);
                    e1x*=inv; e1y*=inv; e1z*=inv;
                    float ux=bx-ax, uy=by-ay, uz=bz-az;
                    float nx=uy*e1z-uz*e1y, ny=uz*e1x-ux*e1z, nz=ux*e1y-uy*e1x;
                    inv = rsqrtf(nx*nx+ny*ny+nz*nz + 1e-12f);
                    nx*=inv; ny*=inv; nz*=inv;
                    float e2x=ny*e1z-nz*e1y, e2y=nz*e1x-nx*e1z, e2z=nx*e1y-ny*e1x;
                    int hyb = hyb_arr[bt*MA_+i];
                    float chi0, chi1;
                    if      (hyb == 0) { chi0=sp2t[0];  chi1=sp2t[1];  }
                    else if (hyb == 1) { chi0=sp3t[0];  chi1=sp3t[1];  }
                    else               { chi0=ringt[0]; chi1=ringt[1]; }
                    float ct=cosf(wang), st=sinf(wang);
                    float a1 = -wdist*ct;
                    float b0 = wdist*st*cosf(chi0), c0 = wdist*st*sinf(chi0);
                    float b1 = wdist*st*cosf(chi1), c1 = wdist*st*sinf(chi1);
                    xp0=cx; xp1=cy; xp2=cz;
                    w00 = cx + a1*e1x + b0*e2x + c0*nx;
                    w01 = cy + a1*e1y + b0*e2y + c0*ny;
                    w02 = cz + a1*e1z + b0*e2z + c0*nz;
                    w10 = cx + a1*e1x + b1*e2x + c1*nx;
                    w11 = cy + a1*e1y + b1*e2y + c1*ny;
                    w12 = cz + a1*e1z + b1*e2z + c1*nz;
                }
            }
            st_act[slot] = active;
            if (active) {
                float4 q = lkp4[bt*A_+ai];         // ri,dgi,lam,vol
                st_pol[slot] = make_float4(xp0, xp1, xp2, q.x);
                st_w0[slot]  = make_float4(w00, w01, w02, C_LK*q.y/q.z);
                st_w1[slot]  = make_float4(w10, w11, w12, 1.0f/q.z);
                st_a[slot]   = ai*A_;
            }
        }
    } else {
        // stage this CTA's j range: coords+rj (H -> far sentinel), vol
        int jb = c*JCHUNK_;
        const float* cp = coords + (size_t)p*N_*3;
        for (int i = tid; i < JCHUNK_; i += STG_) {
            int j   = jb + i;
            int bj  = j >> 5;
            int a   = j & 31;
            int btj = s_bt[bj];
            float4 q = lkp4[btj*A_+a];
            bool hyd = (is_h[btj*A_+a] != 0);
            float x = cp[3*j], y = cp[3*j+1], z = cp[3*j+2];
            s_xyz[i] = hyd ? make_float4(-1e6f,-1e6f,-1e6f,0.f)
                           : make_float4(x, y, z, q.x);
            s_vol[i] = hyd ? 0.f : q.w;
        }
    }
    __syncthreads();
    if (tid == 0) {                         // compact + pad to bucket with dummies
        int n = 0;
        for (int t = 0; t < NPOL_; t++) if (st_act[t]) {
            s_pol[n]=st_pol[t]; s_w0[n]=st_w0[t]; s_w1[n]=st_w1[t]; s_arow[n]=st_a[t];
            n++;
        }
        s_npol = n;
        for (; n < NPOL_; n++) {
            s_pol[n]=make_float4(1e6f,1e6f,1e6f,0.f);   // never passes cutoff
            s_w0[n]=make_float4(0,0,0,0); s_w1[n]=make_float4(0,0,0,1.f);
            s_arow[n]=0;
        }
    }
    __syncthreads();
    // same-block separation bitmasks: warp k -> pol k, lane a -> atom a
    if (tid < NPOL_*32) {
        int k = tid >> 5, a = tid & 31;
        unsigned mk = __ballot_sync(FULLM, pathd[bt*A_*A_ + s_arow[k] + a] >= 4);
        if (a == 0) s_pmask[k] = mk;
    }
    __syncthreads();

    float cutoff2 = lkgp[0]*lkgp[0];
    float ramp2   = lkgp[1];
    float d2lr    = lkgp[2] + ramp2;
    float invramp = 1.0f/ramp2;

    int jbase = c*JCHUNK_;
    int warp  = tid >> 5;
    int lane  = tid & 31;
    int np    = s_npol;                     // CTA-uniform

    float sum0 = 0.f, sum1 = 0.f;
    if (np <= 4)
        scan_phase<4>(s_pol, s_w0, s_w1, s_pmask, s_sepok, s_xyz, s_vol,
                      b, jbase, warp, lane, cutoff2, d2lr, invramp, tid, sum0, sum1);
    else if (np <= 6)
        scan_phase<6>(s_pol, s_w0, s_w1, s_pmask, s_sepok, s_xyz, s_vol,
                      b, jbase, warp, lane, cutoff2, d2lr, invramp, tid, sum0, sum1);
    else
        scan_phase<8>(s_pol, s_w0, s_w1, s_pmask, s_sepok, s_xyz, s_vol,
                      b, jbase, warp, lane, cutoff2, d2lr, invramp, tid, sum0, sum1);

    // deterministic CTA reduction (fp64)
    double d0 = sum0, d1 = sum1;
    for (int off = 16; off; off >>= 1) {
        d0 += __shfl_xor_sync(FULLM, d0, off);
        d1 += __shfl_xor_sync(FULLM, d1, off);
    }
    if (lane == 0) { s_red[warp][0]=d0; s_red[warp][1]=d1; }
    __syncthreads();
    if (tid == 0) {
        double a=0, cc=0;
        #pragma unroll
        for (int w = 0; w < NW_; w++) { a+=s_red[w][0]; cc+=s_red[w][1]; }
        g_partial[cta*2]   = a;
        g_partial[cta*2+1] = cc;
    }

    // ---- last-CTA final reduce (fixed-order -> deterministic) ----
    __shared__ bool s_last;
    __threadfence();
    if (tid == 0)
        s_last = (atomicAdd(&g_done, 1u) == (unsigned)(gridDim.x - 1));
    __syncthreads();
    if (!s_last) return;

    __shared__ double rr0[TPB_], rr1[TPB_];
    for (int pp = 0; pp < P_; pp++) {
        double a = 0, cc = 0;
        for (int i = tid; i < B_*CH_; i += TPB_) {
            a  += g_partial[(pp*B_*CH_+i)*2];
            cc += g_partial[(pp*B_*CH_+i)*2+1];
        }
        rr0[tid] = a; rr1[tid] = cc;
        __syncthreads();
        for (int s = TPB_/2; s >= 1; s >>= 1) {
            if (tid < s) { rr0[tid] += rr0[tid+s]; rr1[tid] += rr1[tid+s]; }
            __syncthreads();
        }
        if (tid == 0) {
            out[pp]     = (float)rr0[0];
            out[P_+pp]  = (float)rr1[0];
        }
        __syncthreads();
    }
    if (tid == 0) g_done = 0;            // reset for next graph replay
}

extern "C" void kernel_launch(void* const* d_in, const int* in_sizes, int n_in,
                              void* d_out, int out_size) {
    const float* coords  = (const float*)d_in[0];
    const int*   btype   = (const int*)  d_in[1];
    const int*   minsep  = (const int*)  d_in[2];
    // d_in[3] = bt_n_atoms (unused: all blocks have A_ atoms)
    const int*   bonds   = (const int*)  d_in[4];
    const int*   ranges  = (const int*)  d_in[5];
    const int*   n_donH  = (const int*)  d_in[6];
    const int*   n_acc   = (const int*)  d_in[7];
    const int*   donH_i  = (const int*)  d_in[8];
    const int*   don_hvy = (const int*)  d_in[9];
    const int*   acc_i   = (const int*)  d_in[10];
    const int*   hyb     = (const int*)  d_in[11];
    const int*   is_h    = (const int*)  d_in[12];
    const float* lkp     = (const float*)d_in[13];
    const int*   pathd   = (const int*)  d_in[14];
    const float* lkgp    = (const float*)d_in[15];
    const float* wgp     = (const float*)d_in[16];
    const float* sp2     = (const float*)d_in[17];
    const float* sp3     = (const float*)d_in[18];
    const float* ringt   = (const float*)d_in[19];

    lkball_kernel<<<P_*B_*CH_, TPB_>>>(coords, btype, minsep, bonds, ranges,
                                       n_donH, n_acc, donH_i, don_hvy, acc_i, hyb,
                                       lkp, is_h, pathd, lkgp, wgp, sp2, sp3, ringt,
                                       (float*)d_out);
}